// round 14
// baseline (speedup 1.0000x reference)
#include <cuda_runtime.h>
#include <cuda_fp16.h>
#include <math.h>
#include <stdint.h>

// Problem constants
constexpr int DIM  = 1024;
constexpr int NH   = 16;
constexpr int HDm  = 64;
constexpr int FFD  = 4096;
constexpr int BATCH= 2;
constexpr int SEQ  = 2048;
constexpr int MTOK = BATCH * SEQ;   // 4096
constexpr int QKVD = 3 * DIM;       // 3072

// ---------------------------------------------------------------------------
// helpers
// ---------------------------------------------------------------------------
__device__ __forceinline__ uint32_t smem_to_u32(const void* p) {
    uint32_t a;
    asm("{ .reg .u64 t; cvta.to.shared.u64 t, %1; cvt.u32.u64 %0, t; }"
        : "=r"(a) : "l"(p));
    return a;
}

__device__ __forceinline__ void ldsm_x4(uint32_t* r, uint32_t addr) {
    asm volatile("ldmatrix.sync.aligned.m8n8.x4.shared.b16 {%0,%1,%2,%3}, [%4];"
                 : "=r"(r[0]), "=r"(r[1]), "=r"(r[2]), "=r"(r[3]) : "r"(addr));
}

__device__ __forceinline__ void ldsm_x4_trans(uint32_t* r, uint32_t addr) {
    asm volatile("ldmatrix.sync.aligned.m8n8.x4.trans.shared.b16 {%0,%1,%2,%3}, [%4];"
                 : "=r"(r[0]), "=r"(r[1]), "=r"(r[2]), "=r"(r[3]) : "r"(addr));
}

__device__ __forceinline__ void mma16816(float* c, const uint32_t* a, const uint32_t* b) {
    asm volatile(
        "mma.sync.aligned.m16n8k16.row.col.f32.f16.f16.f32 "
        "{%0,%1,%2,%3}, {%4,%5,%6,%7}, {%8,%9}, {%0,%1,%2,%3};"
        : "+f"(c[0]), "+f"(c[1]), "+f"(c[2]), "+f"(c[3])
        : "r"(a[0]), "r"(a[1]), "r"(a[2]), "r"(a[3]), "r"(b[0]), "r"(b[1]));
}

__device__ __forceinline__ void cpa16(uint32_t dst, const void* src) {
    asm volatile("cp.async.ca.shared.global [%0], [%1], 16;" :: "r"(dst), "l"(src));
}

__device__ __forceinline__ uint32_t pk2(float a, float b) {
    __half2 t(__float2half_rn(a), __float2half_rn(b));
    return *(uint32_t*)&t;
}

// fast GELU: x * sigmoid(2t), t = 0.7978845608*(x + 0.044715 x^3)
__device__ __forceinline__ float gelu_fast(float x) {
    float t2 = 1.5957691216f * x * (1.f + 0.044715f * x * x);   // 2t
    return __fdividef(x, 1.f + __expf(-t2));
}

// ---------------------------------------------------------------------------
// scratch (device globals; no allocation allowed)
// ---------------------------------------------------------------------------
__device__ __align__(256) float g_tmp[MTOK * DIM];
__device__ __align__(256) float g_x1 [MTOK * DIM];

__device__ __align__(256) __half g_x   [MTOK * DIM];
__device__ __align__(256) __half g_qkv [MTOK * QKVD];    // fused q|k|v (q pre-scaled 1/8)
__device__ __align__(256) __half g_ctx [MTOK * DIM];
__device__ __align__(256) __half g_x1h [MTOK * DIM];
__device__ __align__(256) __half g_h   [MTOK * FFD];
__device__ __align__(256) __half g_wqkv[QKVD * DIM];     // [3072][1024]
__device__ __align__(256) __half g_wo  [DIM * DIM];
__device__ __align__(256) __half g_w1  [DIM * FFD];      // [FFD][DIM]
__device__ __align__(256) __half g_w2  [FFD * DIM];      // [DIM][FFD]
__device__ __align__(256) float  g_bqkv[QKVD];

// ---------------------------------------------------------------------------
// fused prep kernel: all weight transposes + x convert + bias concat
// ---------------------------------------------------------------------------
constexpr int NB_X  = (MTOK * DIM) / 1024;      // 4096
constexpr int NB_B  = 3;
constexpr int NB_SQ = (DIM/32) * (DIM/32);      // 1024
constexpr int NB_W1 = (FFD/32) * (DIM/32);      // 4096
constexpr int NB_W2 = (DIM/32) * (FFD/32);      // 4096
constexpr int NB_PREP = NB_X + NB_B + 4 * NB_SQ + NB_W1 + NB_W2;  // 16387

__device__ __forceinline__ void tr_tile(const float* __restrict__ in,
                                        __half* __restrict__ o,
                                        int K, int N, int t, float (*ts)[33])
{
    const int tn = N / 32;
    const int n0 = (t % tn) * 32, k0 = (t / tn) * 32;
    const int tx = threadIdx.x & 31, ty = threadIdx.x >> 5;
    #pragma unroll
    for (int j = 0; j < 32; j += 8)
        ts[ty + j][tx] = in[(size_t)(k0 + ty + j) * N + n0 + tx];
    __syncthreads();
    #pragma unroll
    for (int j = 0; j < 32; j += 8) {
        int n = n0 + ty + j, k = k0 + tx;
        o[(size_t)n * K + k] = __float2half_rn(ts[tx][ty + j]);
    }
}

__global__ __launch_bounds__(256)
void prep_all(const float* __restrict__ x,
              const float* __restrict__ wq, const float* __restrict__ wk,
              const float* __restrict__ wv, const float* __restrict__ wo,
              const float* __restrict__ w1, const float* __restrict__ w2,
              const float* __restrict__ bq, const float* __restrict__ bk,
              const float* __restrict__ bv,
              __half* __restrict__ xh, __half* __restrict__ wqkvh,
              __half* __restrict__ woh, __half* __restrict__ w1h,
              __half* __restrict__ w2h, float* __restrict__ bqkv)
{
    __shared__ float ts[32][33];
    int bid = blockIdx.x;
    if (bid < NB_X) {
        int i = (bid * 256 + threadIdx.x) * 4;
        float4 v = *(const float4*)(x + i);
        *(uint2*)(xh + i) = make_uint2(pk2(v.x, v.y), pk2(v.z, v.w));
        return;
    }
    bid -= NB_X;
    if (bid < NB_B) {
        int i = bid * 1024 + threadIdx.x * 4;
        #pragma unroll
        for (int j = 0; j < 4; j++) {
            int idx = i + j;
            if (idx < QKVD)
                bqkv[idx] = (idx < DIM) ? bq[idx]
                          : ((idx < 2 * DIM) ? bk[idx - DIM] : bv[idx - 2 * DIM]);
        }
        return;
    }
    bid -= NB_B;
    if (bid < NB_SQ)       { tr_tile(wq, wqkvh,                 DIM, DIM, bid, ts); return; }
    bid -= NB_SQ;
    if (bid < NB_SQ)       { tr_tile(wk, wqkvh + DIM * DIM,     DIM, DIM, bid, ts); return; }
    bid -= NB_SQ;
    if (bid < NB_SQ)       { tr_tile(wv, wqkvh + 2 * DIM * DIM, DIM, DIM, bid, ts); return; }
    bid -= NB_SQ;
    if (bid < NB_SQ)       { tr_tile(wo, woh, DIM, DIM, bid, ts); return; }
    bid -= NB_SQ;
    if (bid < NB_W1)       { tr_tile(w1, w1h, DIM, FFD, bid, ts); return; }
    bid -= NB_W1;
    tr_tile(w2, w2h, FFD, DIM, bid, ts);
}

// ---------------------------------------------------------------------------
// HMMA fp16 GEMM, BK=64, 3-stage cp.async pipeline, 2 CTAs/SM.
// 128 threads (4 warps, 2x2), 128x128 CTA tile, 64x64 warp tile.
// QSCALE: multiply outputs in cols [0, DIM) by 1/8 before fp16 emit.
// ---------------------------------------------------------------------------
constexpr int HG_RSTRIDE = 144;                // 64 fp16 = 128 B + 16 pad
constexpr int HG_TILE    = 128 * HG_RSTRIDE;   // 18432 B
constexpr int HG_STAGE   = 2 * HG_TILE;        // 36864 B
constexpr int HG_SMEM    = 3 * HG_STAGE;       // 110592 B (2 CTAs = 216 KB)

__device__ __forceinline__ void hg_load_tile(const __half* __restrict__ src,
                                             int rowBase, int K, int k0,
                                             uint32_t dstBase, int tid)
{
    // 128 rows x 64 fp16 = 1024 16B-chunks, 128 threads -> 8 iters
    #pragma unroll
    for (int i = 0; i < 8; i++) {
        int c = tid + i * 128;
        int row = c >> 3, cc = c & 7;
        uint32_t dst = dstBase + row * HG_RSTRIDE + cc * 16;
        const void* s = src + (size_t)(rowBase + row) * K + k0 + cc * 8;
        cpa16(dst, s);
    }
}

template<bool GELU, bool WRITE_F32, bool EMIT, bool QSCALE>
__global__ __launch_bounds__(128, 2)
void hmma_gemm(const __half* __restrict__ A, const __half* __restrict__ B,
               const float* __restrict__ bias, float* __restrict__ C,
               __half* __restrict__ Ch, int M, int N, int K)
{
    extern __shared__ char smem[];
    const uint32_t sb = smem_to_u32(smem);
    const int tid = threadIdx.x, wid = tid >> 5, lane = tid & 31;
    const int warpM = wid >> 1, warpN = wid & 1;       // 2x2 warp grid
    const int bRow = blockIdx.y * 128, bCol = blockIdx.x * 128;

    float acc[4][8][4];
    #pragma unroll
    for (int m = 0; m < 4; m++)
        #pragma unroll
        for (int n = 0; n < 8; n++)
            #pragma unroll
            for (int e = 0; e < 4; e++) acc[m][n][e] = 0.f;

    #pragma unroll
    for (int p = 0; p < 2; p++) {
        uint32_t base = sb + p * HG_STAGE;
        hg_load_tile(A, bRow, K, p * 64, base, tid);
        hg_load_tile(B, bCol, K, p * 64, base + HG_TILE, tid);
        asm volatile("cp.async.commit_group;");
    }

    const int nk = K >> 6;
    for (int ks = 0; ks < nk; ks++) {
        if (ks == nk - 1) { asm volatile("cp.async.wait_group 0;"); }
        else              { asm volatile("cp.async.wait_group 1;"); }
        __syncthreads();

        if (ks + 2 < nk) {
            uint32_t base = sb + (uint32_t)((ks + 2) % 3) * HG_STAGE;
            const int k0 = (ks + 2) << 6;
            hg_load_tile(A, bRow, K, k0, base, tid);
            hg_load_tile(B, bCol, K, k0, base + HG_TILE, tid);
            asm volatile("cp.async.commit_group;");
        }

        const uint32_t stg = sb + (uint32_t)(ks % 3) * HG_STAGE;
        #pragma unroll
        for (int h = 0; h < 4; h++) {
            const int ke = h * 16;
            uint32_t aF[4][4], bF[8][2];
            #pragma unroll
            for (int m = 0; m < 4; m++) {
                uint32_t ra = stg
                    + (warpM * 64 + m * 16 + (lane & 15)) * HG_RSTRIDE
                    + (ke + (lane >> 4) * 8) * 2;
                ldsm_x4(aF[m], ra);
            }
            #pragma unroll
            for (int jp = 0; jp < 4; jp++) {
                uint32_t rb = stg + HG_TILE
                    + (warpN * 64 + jp * 16 + (lane >> 4) * 8 + (lane & 7)) * HG_RSTRIDE
                    + (ke + ((lane >> 3) & 1) * 8) * 2;
                uint32_t t4[4];
                ldsm_x4(t4, rb);
                bF[2*jp][0] = t4[0]; bF[2*jp][1] = t4[1];
                bF[2*jp+1][0] = t4[2]; bF[2*jp+1][1] = t4[3];
            }
            #pragma unroll
            for (int m = 0; m < 4; m++)
                #pragma unroll
                for (int n = 0; n < 8; n++)
                    mma16816(acc[m][n], aF[m], bF[n]);
        }
    }

    #pragma unroll
    for (int m = 0; m < 4; m++) {
        #pragma unroll
        for (int half = 0; half < 2; half++) {
            const size_t row = bRow + warpM * 64 + m * 16 + (lane >> 2) + half * 8;
            #pragma unroll
            for (int n = 0; n < 8; n++) {
                const int col = bCol + warpN * 64 + n * 8 + (lane & 3) * 2;
                float v0 = acc[m][n][half * 2 + 0] + bias[col];
                float v1 = acc[m][n][half * 2 + 1] + bias[col + 1];
                if (GELU) {
                    v0 = gelu_fast(v0);
                    v1 = gelu_fast(v1);
                }
                if (WRITE_F32) {
                    float2 w; w.x = v0; w.y = v1;
                    *(float2*)(C + row * N + col) = w;
                }
                if (EMIT) {
                    if (QSCALE && col < DIM) { v0 *= 0.125f; v1 *= 0.125f; }
                    *(uint32_t*)(Ch + row * N + col) = pk2(v0, v1);
                }
            }
        }
    }
}

// ---------------------------------------------------------------------------
// Flash attention, HMMA fp16, double-buffered K/V, fixed-max softmax.
// 256 threads / 8 warps, 16 q-rows per warp (R12 configuration — softmax-chain
// latency is the limiter, more warps hide it better than higher mma intensity).
// Q pre-scaled by 1/8 at QKV emit.
// ---------------------------------------------------------------------------
constexpr int FA_ROW   = 144;
constexpr int FA_Q     = 0;
constexpr int FA_KV    = FA_Q + 128 * FA_ROW;   // 18432
constexpr int FA_KVT   = 64 * FA_ROW;           // 9216
constexpr int FA_KVSTG = 2 * FA_KVT;            // 18432
constexpr int FA_MSK   = FA_KV + 2 * FA_KVSTG;  // 55296
constexpr int FA_SMEM  = FA_MSK + 2 * 64 * 4;   // 55808

__global__ __launch_bounds__(256, 2)
void flash_attn_fp16(const __half* __restrict__ QKV, const int* __restrict__ amask,
                     __half* __restrict__ Ctx)
{
    extern __shared__ char smc[];
    const uint32_t sb = smem_to_u32(smc);
    const int tid = threadIdx.x, wid = tid >> 5, lane = tid & 31;
    const int bh = blockIdx.y, b = bh >> 4, h = bh & 15;
    const int q0 = blockIdx.x * 128;

    const __half* Qg = QKV + (size_t)(b * SEQ + q0) * QKVD + h * HDm;
    const __half* Kg = QKV + (size_t)(b * SEQ) * QKVD + DIM + h * HDm;
    const __half* Vg = QKV + (size_t)(b * SEQ) * QKVD + 2 * DIM + h * HDm;
    int* msk = (int*)(smc + FA_MSK);

    #pragma unroll
    for (int i = 0; i < 4; i++) {
        int c = tid + i * 256; int r = c >> 3, cc = c & 7;
        cpa16(sb + FA_Q + r * FA_ROW + cc * 16, Qg + (size_t)r * QKVD + cc * 8);
    }
    {
        uint32_t kv0 = sb + FA_KV;
        #pragma unroll
        for (int i = 0; i < 2; i++) {
            int c = tid + i * 256; int r = c >> 3, cc = c & 7;
            cpa16(kv0 + 0 * FA_KVT + r * FA_ROW + cc * 16, Kg + (size_t)r * QKVD + cc * 8);
            cpa16(kv0 + 1 * FA_KVT + r * FA_ROW + cc * 16, Vg + (size_t)r * QKVD + cc * 8);
        }
    }
    if (tid < 64) msk[tid] = amask[b * SEQ + tid];
    asm volatile("cp.async.commit_group;");

    float l0 = 0.f, l1 = 0.f;
    float o[8][4];
    #pragma unroll
    for (int nt = 0; nt < 8; nt++)
        #pragma unroll
        for (int e = 0; e < 4; e++) o[nt][e] = 0.f;

    const int kb = 2 * (lane & 3);
    constexpr int NT = SEQ / 64;   // 32

    for (int t = 0; t < NT; t++) {
        asm volatile("cp.async.wait_group 0;");
        __syncthreads();

        if (t + 1 < NT) {
            const int k1 = (t + 1) * 64;
            uint32_t kvn = sb + FA_KV + ((t + 1) & 1) * FA_KVSTG;
            #pragma unroll
            for (int i = 0; i < 2; i++) {
                int c = tid + i * 256; int r = c >> 3, cc = c & 7;
                cpa16(kvn + 0 * FA_KVT + r * FA_ROW + cc * 16, Kg + (size_t)(k1 + r) * QKVD + cc * 8);
                cpa16(kvn + 1 * FA_KVT + r * FA_ROW + cc * 16, Vg + (size_t)(k1 + r) * QKVD + cc * 8);
            }
            if (tid < 64) msk[((t + 1) & 1) * 64 + tid] = amask[b * SEQ + k1 + tid];
            asm volatile("cp.async.commit_group;");
        }

        const uint32_t kvb = sb + FA_KV + (t & 1) * FA_KVSTG;
        const int* mrow = msk + (t & 1) * 64;

        // ---- S = Q K^T (Q pre-scaled) ----
        float sacc[8][4];
        #pragma unroll
        for (int nt = 0; nt < 8; nt++)
            #pragma unroll
            for (int e = 0; e < 4; e++) sacc[nt][e] = 0.f;

        #pragma unroll
        for (int kk = 0; kk < 4; kk++) {
            uint32_t aF[4];
            uint32_t ra = sb + FA_Q
                + (wid * 16 + (lane & 15)) * FA_ROW
                + (kk * 16 + (lane >> 4) * 8) * 2;
            ldsm_x4(aF, ra);
            #pragma unroll
            for (int jp = 0; jp < 4; jp++) {
                uint32_t rb = kvb
                    + (jp * 16 + (lane >> 4) * 8 + (lane & 7)) * FA_ROW
                    + (kk * 16 + ((lane >> 3) & 1) * 8) * 2;
                uint32_t bF[4];
                ldsm_x4(bF, rb);
                mma16816(sacc[2*jp],   aF, &bF[0]);
                mma16816(sacc[2*jp+1], aF, &bF[2]);
            }
        }

        // ---- fixed-max softmax: p = exp(s) (masked -> 0) ----
        float s0 = 0.f, s1 = 0.f;
        #pragma unroll
        for (int nt = 0; nt < 8; nt++) {
            bool z0 = mrow[nt * 8 + kb] == 0, z1 = mrow[nt * 8 + kb + 1] == 0;
            float p0 = z0 ? 0.f : __expf(sacc[nt][0]);
            float p1 = z1 ? 0.f : __expf(sacc[nt][1]);
            float p2 = z0 ? 0.f : __expf(sacc[nt][2]);
            float p3 = z1 ? 0.f : __expf(sacc[nt][3]);
            sacc[nt][0] = p0; sacc[nt][1] = p1; sacc[nt][2] = p2; sacc[nt][3] = p3;
            s0 += p0 + p1; s1 += p2 + p3;
        }
        s0 += __shfl_xor_sync(0xffffffffu, s0, 1);
        s0 += __shfl_xor_sync(0xffffffffu, s0, 2);
        s1 += __shfl_xor_sync(0xffffffffu, s1, 1);
        s1 += __shfl_xor_sync(0xffffffffu, s1, 2);
        l0 += s0; l1 += s1;

        // ---- O += P V  (V token-major, ldmatrix.trans) ----
        #pragma unroll
        for (int j = 0; j < 4; j++) {
            uint32_t pF[4];
            pF[0] = pk2(sacc[2*j][0],   sacc[2*j][1]);
            pF[1] = pk2(sacc[2*j][2],   sacc[2*j][3]);
            pF[2] = pk2(sacc[2*j+1][0], sacc[2*j+1][1]);
            pF[3] = pk2(sacc[2*j+1][2], sacc[2*j+1][3]);
            #pragma unroll
            for (int t4i = 0; t4i < 4; t4i++) {
                uint32_t rb = kvb + FA_KVT
                    + (j * 16 + ((lane >> 3) & 1) * 8 + (lane & 7)) * FA_ROW
                    + (t4i * 16 + (lane >> 4) * 8) * 2;
                uint32_t bF[4];
                ldsm_x4_trans(bF, rb);
                mma16816(o[2*t4i],   pF, &bF[0]);
                mma16816(o[2*t4i+1], pF, &bF[2]);
            }
        }
    }

    const float i0 = 1.f / l0, i1 = 1.f / l1;
    const size_t r0 = (size_t)b * SEQ + q0 + wid * 16 + (lane >> 2);
    const size_t r1 = r0 + 8;
    #pragma unroll
    for (int nt = 0; nt < 8; nt++) {
        const int col = h * HDm + nt * 8 + kb;
        *(uint32_t*)(Ctx + r0 * DIM + col) = pk2(o[nt][0] * i0, o[nt][1] * i0);
        *(uint32_t*)(Ctx + r1 * DIM + col) = pk2(o[nt][2] * i1, o[nt][3] * i1);
    }
}

// ---------------- LN building block --------------------------------------
__device__ __forceinline__ void block_ln_stats(float4 v, float& mean, float& rstd,
                                               float eps, float* ssum, float* ssq,
                                               float* stats, int tid)
{
    float sum = v.x + v.y + v.z + v.w;
    float sq  = v.x * v.x + v.y * v.y + v.z * v.z + v.w * v.w;
    #pragma unroll
    for (int mm = 16; mm; mm >>= 1) {
        sum += __shfl_xor_sync(0xffffffffu, sum, mm);
        sq  += __shfl_xor_sync(0xffffffffu, sq,  mm);
    }
    const int wid = tid >> 5, lane = tid & 31;
    if (lane == 0) { ssum[wid] = sum; ssq[wid] = sq; }
    __syncthreads();
    if (tid == 0) {
        float S = 0.f, Qq = 0.f;
        #pragma unroll
        for (int i = 0; i < 8; i++) { S += ssum[i]; Qq += ssq[i]; }
        float mu = S * (1.f / DIM);
        float var = fmaxf(Qq * (1.f / DIM) - mu * mu, 0.f);
        stats[0] = mu;
        stats[1] = rsqrtf(var + eps);
    }
    __syncthreads();
    mean = stats[0]; rstd = stats[1];
}

template<bool EMIT>
__global__ __launch_bounds__(256)
void ln_residual(const float* __restrict__ A, const float* __restrict__ Bv,
                 const float* __restrict__ g, const float* __restrict__ be,
                 float* __restrict__ out, __half* __restrict__ oh, float eps)
{
    const int row = blockIdx.x;
    const int tid = threadIdx.x;
    __shared__ float ssum[8], ssq[8], stats[2];
    const float4 va = ((const float4*)(A  + (size_t)row * DIM))[tid];
    const float4 vb = ((const float4*)(Bv + (size_t)row * DIM))[tid];
    float4 v;
    v.x = va.x + vb.x; v.y = va.y + vb.y;
    v.z = va.z + vb.z; v.w = va.w + vb.w;
    float mean, rstd;
    block_ln_stats(v, mean, rstd, eps, ssum, ssq, stats, tid);
    const float4 gg = ((const float4*)g)[tid];
    const float4 bb = ((const float4*)be)[tid];
    float4 r;
    r.x = (v.x - mean) * rstd * gg.x + bb.x;
    r.y = (v.y - mean) * rstd * gg.y + bb.y;
    r.z = (v.z - mean) * rstd * gg.z + bb.z;
    r.w = (v.w - mean) * rstd * gg.w + bb.w;
    ((float4*)(out + (size_t)row * DIM))[tid] = r;
    if (EMIT) {
        ((uint2*)(oh + (size_t)row * DIM))[tid] =
            make_uint2(pk2(r.x, r.y), pk2(r.z, r.w));
    }
}

__global__ __launch_bounds__(256)
void ln_double(const float* __restrict__ Tmp, const float* __restrict__ X1,
               const float* __restrict__ gf, const float* __restrict__ bf,
               const float* __restrict__ g2, const float* __restrict__ b2,
               float* __restrict__ out)
{
    const int row = blockIdx.x;
    const int tid = threadIdx.x;
    __shared__ float ssum[8], ssq[8], stats[2];
    const float4 vt = ((const float4*)(Tmp + (size_t)row * DIM))[tid];
    const float4 vx = ((const float4*)(X1  + (size_t)row * DIM))[tid];
    float4 v;
    v.x = vt.x + vx.x; v.y = vt.y + vx.y;
    v.z = vt.z + vx.z; v.w = vt.w + vx.w;
    float mean, rstd;
    block_ln_stats(v, mean, rstd, 1e-12f, ssum, ssq, stats, tid);
    const float4 gg = ((const float4*)gf)[tid];
    const float4 bb = ((const float4*)bf)[tid];
    float4 u;
    u.x = (v.x - mean) * rstd * gg.x + bb.x + vx.x;
    u.y = (v.y - mean) * rstd * gg.y + bb.y + vx.y;
    u.z = (v.z - mean) * rstd * gg.z + bb.z + vx.z;
    u.w = (v.w - mean) * rstd * gg.w + bb.w + vx.w;
    __syncthreads();
    float mean2, rstd2;
    block_ln_stats(u, mean2, rstd2, 1e-5f, ssum, ssq, stats, tid);
    const float4 g2v = ((const float4*)g2)[tid];
    const float4 b2v = ((const float4*)b2)[tid];
    float4 r;
    r.x = (u.x - mean2) * rstd2 * g2v.x + b2v.x;
    r.y = (u.y - mean2) * rstd2 * g2v.y + b2v.y;
    r.z = (u.z - mean2) * rstd2 * g2v.z + b2v.z;
    r.w = (u.w - mean2) * rstd2 * g2v.w + b2v.w;
    ((float4*)(out + (size_t)row * DIM))[tid] = r;
}

// ---------------- launch ----------------------------------------------------
extern "C" void kernel_launch(void* const* d_in, const int* in_sizes, int n_in,
                              void* d_out, int out_size)
{
    const float* x     = (const float*)d_in[0];
    const int*   amask = (const int*  )d_in[1];
    const float* wq = (const float*)d_in[2];
    const float* bq = (const float*)d_in[3];
    const float* wk = (const float*)d_in[4];
    const float* bk = (const float*)d_in[5];
    const float* wv = (const float*)d_in[6];
    const float* bv = (const float*)d_in[7];
    const float* wo = (const float*)d_in[8];
    const float* bo = (const float*)d_in[9];
    const float* ln1_g = (const float*)d_in[10];
    const float* ln1_b = (const float*)d_in[11];
    const float* w1 = (const float*)d_in[12];
    const float* b1 = (const float*)d_in[13];
    const float* w2 = (const float*)d_in[14];
    const float* b2 = (const float*)d_in[15];
    const float* lnf_g = (const float*)d_in[16];
    const float* lnf_b = (const float*)d_in[17];
    const float* ln2_g = (const float*)d_in[18];
    const float* ln2_b = (const float*)d_in[19];
    float* out = (float*)d_out;

    float *tmp, *x1, *bqkv;
    cudaGetSymbolAddress((void**)&tmp,  g_tmp);
    cudaGetSymbolAddress((void**)&x1,   g_x1);
    cudaGetSymbolAddress((void**)&bqkv, g_bqkv);

    __half *xh,*qkv,*ctxh,*x1h,*hh,*wqkvh,*woh,*w1h,*w2h;
    cudaGetSymbolAddress((void**)&xh,   g_x);
    cudaGetSymbolAddress((void**)&qkv,  g_qkv);
    cudaGetSymbolAddress((void**)&ctxh, g_ctx);
    cudaGetSymbolAddress((void**)&x1h,  g_x1h);
    cudaGetSymbolAddress((void**)&hh,   g_h);
    cudaGetSymbolAddress((void**)&wqkvh,g_wqkv);
    cudaGetSymbolAddress((void**)&woh,  g_wo);
    cudaGetSymbolAddress((void**)&w1h,  g_w1);
    cudaGetSymbolAddress((void**)&w2h,  g_w2);

    cudaFuncSetAttribute(flash_attn_fp16,
                         cudaFuncAttributeMaxDynamicSharedMemorySize, FA_SMEM);
    cudaFuncSetAttribute(hmma_gemm<false,false,true,true>,
                         cudaFuncAttributeMaxDynamicSharedMemorySize, HG_SMEM);
    cudaFuncSetAttribute(hmma_gemm<false,true,false,false>,
                         cudaFuncAttributeMaxDynamicSharedMemorySize, HG_SMEM);
    cudaFuncSetAttribute(hmma_gemm<true,false,true,false>,
                         cudaFuncAttributeMaxDynamicSharedMemorySize, HG_SMEM);

    const dim3 blk(256);
    const dim3 blkG(128);   // GEMM: 4 warps, 64x64 warp tiles, BK=64

    // one fused prep kernel
    prep_all<<<NB_PREP, blk>>>(x, wq, wk, wv, wo, w1, w2, bq, bk, bv,
                               xh, wqkvh, woh, w1h, w2h, bqkv);

    // fused QKV projection (N = 3072), Q columns pre-scaled by 1/8
    hmma_gemm<false,false,true,true><<<dim3(QKVD/128, MTOK/128), blkG, HG_SMEM>>>(
        xh, wqkvh, bqkv, nullptr, qkv, MTOK, QKVD, DIM);

    // attention -> ctx fp16 (256-thread R12 configuration)
    flash_attn_fp16<<<dim3(SEQ/128, BATCH*NH), blk, FA_SMEM>>>(
        qkv, amask, ctxh);

    // O projection + residual LN1 (emit x1 fp16)
    hmma_gemm<false,true,false,false><<<dim3(DIM/128, MTOK/128), blkG, HG_SMEM>>>(
        ctxh, woh, bo, tmp, nullptr, MTOK, DIM, DIM);
    ln_residual<true><<<MTOK, blk>>>(x, tmp, ln1_g, ln1_b, x1, x1h, 1e-5f);

    // FFN
    hmma_gemm<true,false,true,false><<<dim3(FFD/128, MTOK/128), blkG, HG_SMEM>>>(
        x1h, w1h, b1, nullptr, hh, MTOK, FFD, DIM);
    hmma_gemm<false,true,false,false><<<dim3(DIM/128, MTOK/128), blkG, HG_SMEM>>>(
        hh, w2h, b2, tmp, nullptr, MTOK, DIM, FFD);

    // fused LNf + LN2
    ln_double<<<MTOK, blk>>>(tmp, x1, lnf_g, lnf_b, ln2_g, ln2_b, out);
}

// round 15
// speedup vs baseline: 1.6913x; 1.6913x over previous
#include <cuda_runtime.h>
#include <cuda_fp16.h>
#include <math.h>
#include <stdint.h>

// Problem constants
constexpr int DIM  = 1024;
constexpr int NH   = 16;
constexpr int HDm  = 64;
constexpr int FFD  = 4096;
constexpr int BATCH= 2;
constexpr int SEQ  = 2048;
constexpr int MTOK = BATCH * SEQ;   // 4096
constexpr int QKVD = 3 * DIM;       // 3072

// ---------------------------------------------------------------------------
// helpers
// ---------------------------------------------------------------------------
__device__ __forceinline__ uint32_t smem_to_u32(const void* p) {
    uint32_t a;
    asm("{ .reg .u64 t; cvta.to.shared.u64 t, %1; cvt.u32.u64 %0, t; }"
        : "=r"(a) : "l"(p));
    return a;
}

__device__ __forceinline__ void ldsm_x4(uint32_t* r, uint32_t addr) {
    asm volatile("ldmatrix.sync.aligned.m8n8.x4.shared.b16 {%0,%1,%2,%3}, [%4];"
                 : "=r"(r[0]), "=r"(r[1]), "=r"(r[2]), "=r"(r[3]) : "r"(addr));
}

__device__ __forceinline__ void ldsm_x4_trans(uint32_t* r, uint32_t addr) {
    asm volatile("ldmatrix.sync.aligned.m8n8.x4.trans.shared.b16 {%0,%1,%2,%3}, [%4];"
                 : "=r"(r[0]), "=r"(r[1]), "=r"(r[2]), "=r"(r[3]) : "r"(addr));
}

__device__ __forceinline__ void mma16816(float* c, const uint32_t* a, const uint32_t* b) {
    asm volatile(
        "mma.sync.aligned.m16n8k16.row.col.f32.f16.f16.f32 "
        "{%0,%1,%2,%3}, {%4,%5,%6,%7}, {%8,%9}, {%0,%1,%2,%3};"
        : "+f"(c[0]), "+f"(c[1]), "+f"(c[2]), "+f"(c[3])
        : "r"(a[0]), "r"(a[1]), "r"(a[2]), "r"(a[3]), "r"(b[0]), "r"(b[1]));
}

__device__ __forceinline__ void cpa16(uint32_t dst, const void* src) {
    asm volatile("cp.async.ca.shared.global [%0], [%1], 16;" :: "r"(dst), "l"(src));
}

__device__ __forceinline__ uint32_t pk2(float a, float b) {
    __half2 t(__float2half_rn(a), __float2half_rn(b));
    return *(uint32_t*)&t;
}

// fast GELU: x * sigmoid(2t), t = 0.7978845608*(x + 0.044715 x^3)
__device__ __forceinline__ float gelu_fast(float x) {
    float t2 = 1.5957691216f * x * (1.f + 0.044715f * x * x);   // 2t
    return __fdividef(x, 1.f + __expf(-t2));
}

// ---------------------------------------------------------------------------
// scratch (device globals; no allocation allowed)
// ---------------------------------------------------------------------------
__device__ __align__(256) float g_tmp[MTOK * DIM];
__device__ __align__(256) float g_x1 [MTOK * DIM];

__device__ __align__(256) __half g_x   [MTOK * DIM];
__device__ __align__(256) __half g_qkv [MTOK * QKVD];    // fused q|k|v (q pre-scaled 1/8)
__device__ __align__(256) __half g_ctx [MTOK * DIM];
__device__ __align__(256) __half g_x1h [MTOK * DIM];
__device__ __align__(256) __half g_h   [MTOK * FFD];
__device__ __align__(256) __half g_wqkv[QKVD * DIM];     // [3072][1024]
__device__ __align__(256) __half g_wo  [DIM * DIM];
__device__ __align__(256) __half g_w1  [DIM * FFD];      // [FFD][DIM]
__device__ __align__(256) __half g_w2  [FFD * DIM];      // [DIM][FFD]
__device__ __align__(256) float  g_bqkv[QKVD];

// ---------------------------------------------------------------------------
// fused prep kernel: all weight transposes + x convert + bias concat
// ---------------------------------------------------------------------------
constexpr int NB_X  = (MTOK * DIM) / 1024;      // 4096
constexpr int NB_B  = 3;
constexpr int NB_SQ = (DIM/32) * (DIM/32);      // 1024
constexpr int NB_W1 = (FFD/32) * (DIM/32);      // 4096
constexpr int NB_W2 = (DIM/32) * (FFD/32);      // 4096
constexpr int NB_PREP = NB_X + NB_B + 4 * NB_SQ + NB_W1 + NB_W2;  // 16387

__device__ __forceinline__ void tr_tile(const float* __restrict__ in,
                                        __half* __restrict__ o,
                                        int K, int N, int t, float (*ts)[33])
{
    const int tn = N / 32;
    const int n0 = (t % tn) * 32, k0 = (t / tn) * 32;
    const int tx = threadIdx.x & 31, ty = threadIdx.x >> 5;
    #pragma unroll
    for (int j = 0; j < 32; j += 8)
        ts[ty + j][tx] = in[(size_t)(k0 + ty + j) * N + n0 + tx];
    __syncthreads();
    #pragma unroll
    for (int j = 0; j < 32; j += 8) {
        int n = n0 + ty + j, k = k0 + tx;
        o[(size_t)n * K + k] = __float2half_rn(ts[tx][ty + j]);
    }
}

__global__ __launch_bounds__(256)
void prep_all(const float* __restrict__ x,
              const float* __restrict__ wq, const float* __restrict__ wk,
              const float* __restrict__ wv, const float* __restrict__ wo,
              const float* __restrict__ w1, const float* __restrict__ w2,
              const float* __restrict__ bq, const float* __restrict__ bk,
              const float* __restrict__ bv,
              __half* __restrict__ xh, __half* __restrict__ wqkvh,
              __half* __restrict__ woh, __half* __restrict__ w1h,
              __half* __restrict__ w2h, float* __restrict__ bqkv)
{
    __shared__ float ts[32][33];
    int bid = blockIdx.x;
    if (bid < NB_X) {
        int i = (bid * 256 + threadIdx.x) * 4;
        float4 v = *(const float4*)(x + i);
        *(uint2*)(xh + i) = make_uint2(pk2(v.x, v.y), pk2(v.z, v.w));
        return;
    }
    bid -= NB_X;
    if (bid < NB_B) {
        int i = bid * 1024 + threadIdx.x * 4;
        #pragma unroll
        for (int j = 0; j < 4; j++) {
            int idx = i + j;
            if (idx < QKVD)
                bqkv[idx] = (idx < DIM) ? bq[idx]
                          : ((idx < 2 * DIM) ? bk[idx - DIM] : bv[idx - 2 * DIM]);
        }
        return;
    }
    bid -= NB_B;
    if (bid < NB_SQ)       { tr_tile(wq, wqkvh,                 DIM, DIM, bid, ts); return; }
    bid -= NB_SQ;
    if (bid < NB_SQ)       { tr_tile(wk, wqkvh + DIM * DIM,     DIM, DIM, bid, ts); return; }
    bid -= NB_SQ;
    if (bid < NB_SQ)       { tr_tile(wv, wqkvh + 2 * DIM * DIM, DIM, DIM, bid, ts); return; }
    bid -= NB_SQ;
    if (bid < NB_SQ)       { tr_tile(wo, woh, DIM, DIM, bid, ts); return; }
    bid -= NB_SQ;
    if (bid < NB_W1)       { tr_tile(w1, w1h, DIM, FFD, bid, ts); return; }
    bid -= NB_W1;
    tr_tile(w2, w2h, FFD, DIM, bid, ts);
}

// ---------------------------------------------------------------------------
// HMMA fp16 GEMM, BK=32, 3-stage cp.async pipeline, 2 CTAs/SM.
// 128 threads (4 warps, 2x2), 128x128 CTA tile, 64x64 warp tile.
// QSCALE: multiply outputs in cols [0, DIM) by 1/8 before fp16 emit.
// ---------------------------------------------------------------------------
constexpr int HG_RSTRIDE = 80;
constexpr int HG_TILE    = 128 * HG_RSTRIDE;   // 10240 B
constexpr int HG_STAGE   = 2 * HG_TILE;        // 20480 B
constexpr int HG_SMEM    = 3 * HG_STAGE;       // 61440 B (2 CTAs = 120 KB)

__device__ __forceinline__ void hg_load_tile(const __half* __restrict__ src,
                                             int rowBase, int K, int k0,
                                             uint32_t dstBase, int tid)
{
    #pragma unroll
    for (int i = 0; i < 4; i++) {
        int c = tid + i * 128;                 // 0..511, 16B chunks
        int row = c >> 2, cc = c & 3;
        uint32_t dst = dstBase + row * HG_RSTRIDE + cc * 16;
        const void* s = src + (size_t)(rowBase + row) * K + k0 + cc * 8;
        cpa16(dst, s);
    }
}

template<bool GELU, bool WRITE_F32, bool EMIT, bool QSCALE>
__global__ __launch_bounds__(128, 2)
void hmma_gemm(const __half* __restrict__ A, const __half* __restrict__ B,
               const float* __restrict__ bias, float* __restrict__ C,
               __half* __restrict__ Ch, int M, int N, int K)
{
    extern __shared__ char smem[];
    const uint32_t sb = smem_to_u32(smem);
    const int tid = threadIdx.x, wid = tid >> 5, lane = tid & 31;
    const int warpM = wid >> 1, warpN = wid & 1;       // 2x2 warp grid
    const int bRow = blockIdx.y * 128, bCol = blockIdx.x * 128;

    float acc[4][8][4];
    #pragma unroll
    for (int m = 0; m < 4; m++)
        #pragma unroll
        for (int n = 0; n < 8; n++)
            #pragma unroll
            for (int e = 0; e < 4; e++) acc[m][n][e] = 0.f;

    #pragma unroll
    for (int p = 0; p < 2; p++) {
        uint32_t base = sb + p * HG_STAGE;
        hg_load_tile(A, bRow, K, p * 32, base, tid);
        hg_load_tile(B, bCol, K, p * 32, base + HG_TILE, tid);
        asm volatile("cp.async.commit_group;");
    }

    const int nk = K >> 5;
    for (int ks = 0; ks < nk; ks++) {
        if (ks == nk - 1) { asm volatile("cp.async.wait_group 0;"); }
        else              { asm volatile("cp.async.wait_group 1;"); }
        __syncthreads();

        if (ks + 2 < nk) {
            uint32_t base = sb + (uint32_t)((ks + 2) % 3) * HG_STAGE;
            const int k0 = (ks + 2) << 5;
            hg_load_tile(A, bRow, K, k0, base, tid);
            hg_load_tile(B, bCol, K, k0, base + HG_TILE, tid);
            asm volatile("cp.async.commit_group;");
        }

        const uint32_t stg = sb + (uint32_t)(ks % 3) * HG_STAGE;
        #pragma unroll
        for (int h = 0; h < 2; h++) {
            const int ke = h * 16;
            uint32_t aF[4][4], bF[8][2];
            #pragma unroll
            for (int m = 0; m < 4; m++) {
                uint32_t ra = stg
                    + (warpM * 64 + m * 16 + (lane & 15)) * HG_RSTRIDE
                    + (ke + (lane >> 4) * 8) * 2;
                ldsm_x4(aF[m], ra);
            }
            #pragma unroll
            for (int jp = 0; jp < 4; jp++) {
                uint32_t rb = stg + HG_TILE
                    + (warpN * 64 + jp * 16 + (lane >> 4) * 8 + (lane & 7)) * HG_RSTRIDE
                    + (ke + ((lane >> 3) & 1) * 8) * 2;
                uint32_t t4[4];
                ldsm_x4(t4, rb);
                bF[2*jp][0] = t4[0]; bF[2*jp][1] = t4[1];
                bF[2*jp+1][0] = t4[2]; bF[2*jp+1][1] = t4[3];
            }
            #pragma unroll
            for (int m = 0; m < 4; m++)
                #pragma unroll
                for (int n = 0; n < 8; n++)
                    mma16816(acc[m][n], aF[m], bF[n]);
        }
    }

    #pragma unroll
    for (int m = 0; m < 4; m++) {
        #pragma unroll
        for (int half = 0; half < 2; half++) {
            const size_t row = bRow + warpM * 64 + m * 16 + (lane >> 2) + half * 8;
            #pragma unroll
            for (int n = 0; n < 8; n++) {
                const int col = bCol + warpN * 64 + n * 8 + (lane & 3) * 2;
                float v0 = acc[m][n][half * 2 + 0] + bias[col];
                float v1 = acc[m][n][half * 2 + 1] + bias[col + 1];
                if (GELU) {
                    v0 = gelu_fast(v0);
                    v1 = gelu_fast(v1);
                }
                if (WRITE_F32) {
                    float2 w; w.x = v0; w.y = v1;
                    *(float2*)(C + row * N + col) = w;
                }
                if (EMIT) {
                    if (QSCALE && col < DIM) { v0 *= 0.125f; v1 *= 0.125f; }
                    *(uint32_t*)(Ch + row * N + col) = pk2(v0, v1);
                }
            }
        }
    }
}

// ---------------------------------------------------------------------------
// Flash attention, HMMA fp16, double-buffered K/V, fixed-max softmax.
// 256 threads / 8 warps, 16 q-rows per warp (R12 champion configuration).
// Q pre-scaled by 1/8 at QKV emit.
// ---------------------------------------------------------------------------
constexpr int FA_ROW   = 144;
constexpr int FA_Q     = 0;
constexpr int FA_KV    = FA_Q + 128 * FA_ROW;   // 18432
constexpr int FA_KVT   = 64 * FA_ROW;           // 9216
constexpr int FA_KVSTG = 2 * FA_KVT;            // 18432
constexpr int FA_MSK   = FA_KV + 2 * FA_KVSTG;  // 55296
constexpr int FA_SMEM  = FA_MSK + 2 * 64 * 4;   // 55808

__global__ __launch_bounds__(256, 2)
void flash_attn_fp16(const __half* __restrict__ QKV, const int* __restrict__ amask,
                     __half* __restrict__ Ctx)
{
    extern __shared__ char smc[];
    const uint32_t sb = smem_to_u32(smc);
    const int tid = threadIdx.x, wid = tid >> 5, lane = tid & 31;
    const int bh = blockIdx.y, b = bh >> 4, h = bh & 15;
    const int q0 = blockIdx.x * 128;

    const __half* Qg = QKV + (size_t)(b * SEQ + q0) * QKVD + h * HDm;
    const __half* Kg = QKV + (size_t)(b * SEQ) * QKVD + DIM + h * HDm;
    const __half* Vg = QKV + (size_t)(b * SEQ) * QKVD + 2 * DIM + h * HDm;
    int* msk = (int*)(smc + FA_MSK);

    #pragma unroll
    for (int i = 0; i < 4; i++) {
        int c = tid + i * 256; int r = c >> 3, cc = c & 7;
        cpa16(sb + FA_Q + r * FA_ROW + cc * 16, Qg + (size_t)r * QKVD + cc * 8);
    }
    {
        uint32_t kv0 = sb + FA_KV;
        #pragma unroll
        for (int i = 0; i < 2; i++) {
            int c = tid + i * 256; int r = c >> 3, cc = c & 7;
            cpa16(kv0 + 0 * FA_KVT + r * FA_ROW + cc * 16, Kg + (size_t)r * QKVD + cc * 8);
            cpa16(kv0 + 1 * FA_KVT + r * FA_ROW + cc * 16, Vg + (size_t)r * QKVD + cc * 8);
        }
    }
    if (tid < 64) msk[tid] = amask[b * SEQ + tid];
    asm volatile("cp.async.commit_group;");

    float l0 = 0.f, l1 = 0.f;
    float o[8][4];
    #pragma unroll
    for (int nt = 0; nt < 8; nt++)
        #pragma unroll
        for (int e = 0; e < 4; e++) o[nt][e] = 0.f;

    const int kb = 2 * (lane & 3);
    constexpr int NT = SEQ / 64;   // 32

    for (int t = 0; t < NT; t++) {
        asm volatile("cp.async.wait_group 0;");
        __syncthreads();

        if (t + 1 < NT) {
            const int k1 = (t + 1) * 64;
            uint32_t kvn = sb + FA_KV + ((t + 1) & 1) * FA_KVSTG;
            #pragma unroll
            for (int i = 0; i < 2; i++) {
                int c = tid + i * 256; int r = c >> 3, cc = c & 7;
                cpa16(kvn + 0 * FA_KVT + r * FA_ROW + cc * 16, Kg + (size_t)(k1 + r) * QKVD + cc * 8);
                cpa16(kvn + 1 * FA_KVT + r * FA_ROW + cc * 16, Vg + (size_t)(k1 + r) * QKVD + cc * 8);
            }
            if (tid < 64) msk[((t + 1) & 1) * 64 + tid] = amask[b * SEQ + k1 + tid];
            asm volatile("cp.async.commit_group;");
        }

        const uint32_t kvb = sb + FA_KV + (t & 1) * FA_KVSTG;
        const int* mrow = msk + (t & 1) * 64;

        // ---- S = Q K^T (Q pre-scaled) ----
        float sacc[8][4];
        #pragma unroll
        for (int nt = 0; nt < 8; nt++)
            #pragma unroll
            for (int e = 0; e < 4; e++) sacc[nt][e] = 0.f;

        #pragma unroll
        for (int kk = 0; kk < 4; kk++) {
            uint32_t aF[4];
            uint32_t ra = sb + FA_Q
                + (wid * 16 + (lane & 15)) * FA_ROW
                + (kk * 16 + (lane >> 4) * 8) * 2;
            ldsm_x4(aF, ra);
            #pragma unroll
            for (int jp = 0; jp < 4; jp++) {
                uint32_t rb = kvb
                    + (jp * 16 + (lane >> 4) * 8 + (lane & 7)) * FA_ROW
                    + (kk * 16 + ((lane >> 3) & 1) * 8) * 2;
                uint32_t bF[4];
                ldsm_x4(bF, rb);
                mma16816(sacc[2*jp],   aF, &bF[0]);
                mma16816(sacc[2*jp+1], aF, &bF[2]);
            }
        }

        // ---- fixed-max softmax: p = exp(s) (masked -> 0) ----
        float s0 = 0.f, s1 = 0.f;
        #pragma unroll
        for (int nt = 0; nt < 8; nt++) {
            bool z0 = mrow[nt * 8 + kb] == 0, z1 = mrow[nt * 8 + kb + 1] == 0;
            float p0 = z0 ? 0.f : __expf(sacc[nt][0]);
            float p1 = z1 ? 0.f : __expf(sacc[nt][1]);
            float p2 = z0 ? 0.f : __expf(sacc[nt][2]);
            float p3 = z1 ? 0.f : __expf(sacc[nt][3]);
            sacc[nt][0] = p0; sacc[nt][1] = p1; sacc[nt][2] = p2; sacc[nt][3] = p3;
            s0 += p0 + p1; s1 += p2 + p3;
        }
        s0 += __shfl_xor_sync(0xffffffffu, s0, 1);
        s0 += __shfl_xor_sync(0xffffffffu, s0, 2);
        s1 += __shfl_xor_sync(0xffffffffu, s1, 1);
        s1 += __shfl_xor_sync(0xffffffffu, s1, 2);
        l0 += s0; l1 += s1;

        // ---- O += P V  (V token-major, ldmatrix.trans) ----
        #pragma unroll
        for (int j = 0; j < 4; j++) {
            uint32_t pF[4];
            pF[0] = pk2(sacc[2*j][0],   sacc[2*j][1]);
            pF[1] = pk2(sacc[2*j][2],   sacc[2*j][3]);
            pF[2] = pk2(sacc[2*j+1][0], sacc[2*j+1][1]);
            pF[3] = pk2(sacc[2*j+1][2], sacc[2*j+1][3]);
            #pragma unroll
            for (int t4i = 0; t4i < 4; t4i++) {
                uint32_t rb = kvb + FA_KVT
                    + (j * 16 + ((lane >> 3) & 1) * 8 + (lane & 7)) * FA_ROW
                    + (t4i * 16 + (lane >> 4) * 8) * 2;
                uint32_t bF[4];
                ldsm_x4_trans(bF, rb);
                mma16816(o[2*t4i],   pF, &bF[0]);
                mma16816(o[2*t4i+1], pF, &bF[2]);
            }
        }
    }

    const float i0 = 1.f / l0, i1 = 1.f / l1;
    const size_t r0 = (size_t)b * SEQ + q0 + wid * 16 + (lane >> 2);
    const size_t r1 = r0 + 8;
    #pragma unroll
    for (int nt = 0; nt < 8; nt++) {
        const int col = h * HDm + nt * 8 + kb;
        *(uint32_t*)(Ctx + r0 * DIM + col) = pk2(o[nt][0] * i0, o[nt][1] * i0);
        *(uint32_t*)(Ctx + r1 * DIM + col) = pk2(o[nt][2] * i1, o[nt][3] * i1);
    }
}

// ---------------- LN building block --------------------------------------
__device__ __forceinline__ void block_ln_stats(float4 v, float& mean, float& rstd,
                                               float eps, float* ssum, float* ssq,
                                               float* stats, int tid)
{
    float sum = v.x + v.y + v.z + v.w;
    float sq  = v.x * v.x + v.y * v.y + v.z * v.z + v.w * v.w;
    #pragma unroll
    for (int mm = 16; mm; mm >>= 1) {
        sum += __shfl_xor_sync(0xffffffffu, sum, mm);
        sq  += __shfl_xor_sync(0xffffffffu, sq,  mm);
    }
    const int wid = tid >> 5, lane = tid & 31;
    if (lane == 0) { ssum[wid] = sum; ssq[wid] = sq; }
    __syncthreads();
    if (tid == 0) {
        float S = 0.f, Qq = 0.f;
        #pragma unroll
        for (int i = 0; i < 8; i++) { S += ssum[i]; Qq += ssq[i]; }
        float mu = S * (1.f / DIM);
        float var = fmaxf(Qq * (1.f / DIM) - mu * mu, 0.f);
        stats[0] = mu;
        stats[1] = rsqrtf(var + eps);
    }
    __syncthreads();
    mean = stats[0]; rstd = stats[1];
}

template<bool EMIT>
__global__ __launch_bounds__(256)
void ln_residual(const float* __restrict__ A, const float* __restrict__ Bv,
                 const float* __restrict__ g, const float* __restrict__ be,
                 float* __restrict__ out, __half* __restrict__ oh, float eps)
{
    const int row = blockIdx.x;
    const int tid = threadIdx.x;
    __shared__ float ssum[8], ssq[8], stats[2];
    const float4 va = ((const float4*)(A  + (size_t)row * DIM))[tid];
    const float4 vb = ((const float4*)(Bv + (size_t)row * DIM))[tid];
    float4 v;
    v.x = va.x + vb.x; v.y = va.y + vb.y;
    v.z = va.z + vb.z; v.w = va.w + vb.w;
    float mean, rstd;
    block_ln_stats(v, mean, rstd, eps, ssum, ssq, stats, tid);
    const float4 gg = ((const float4*)g)[tid];
    const float4 bb = ((const float4*)be)[tid];
    float4 r;
    r.x = (v.x - mean) * rstd * gg.x + bb.x;
    r.y = (v.y - mean) * rstd * gg.y + bb.y;
    r.z = (v.z - mean) * rstd * gg.z + bb.z;
    r.w = (v.w - mean) * rstd * gg.w + bb.w;
    ((float4*)(out + (size_t)row * DIM))[tid] = r;
    if (EMIT) {
        ((uint2*)(oh + (size_t)row * DIM))[tid] =
            make_uint2(pk2(r.x, r.y), pk2(r.z, r.w));
    }
}

__global__ __launch_bounds__(256)
void ln_double(const float* __restrict__ Tmp, const float* __restrict__ X1,
               const float* __restrict__ gf, const float* __restrict__ bf,
               const float* __restrict__ g2, const float* __restrict__ b2,
               float* __restrict__ out)
{
    const int row = blockIdx.x;
    const int tid = threadIdx.x;
    __shared__ float ssum[8], ssq[8], stats[2];
    const float4 vt = ((const float4*)(Tmp + (size_t)row * DIM))[tid];
    const float4 vx = ((const float4*)(X1  + (size_t)row * DIM))[tid];
    float4 v;
    v.x = vt.x + vx.x; v.y = vt.y + vx.y;
    v.z = vt.z + vx.z; v.w = vt.w + vx.w;
    float mean, rstd;
    block_ln_stats(v, mean, rstd, 1e-12f, ssum, ssq, stats, tid);
    const float4 gg = ((const float4*)gf)[tid];
    const float4 bb = ((const float4*)bf)[tid];
    float4 u;
    u.x = (v.x - mean) * rstd * gg.x + bb.x + vx.x;
    u.y = (v.y - mean) * rstd * gg.y + bb.y + vx.y;
    u.z = (v.z - mean) * rstd * gg.z + bb.z + vx.z;
    u.w = (v.w - mean) * rstd * gg.w + bb.w + vx.w;
    __syncthreads();
    float mean2, rstd2;
    block_ln_stats(u, mean2, rstd2, 1e-5f, ssum, ssq, stats, tid);
    const float4 g2v = ((const float4*)g2)[tid];
    const float4 b2v = ((const float4*)b2)[tid];
    float4 r;
    r.x = (u.x - mean2) * rstd2 * g2v.x + b2v.x;
    r.y = (u.y - mean2) * rstd2 * g2v.y + b2v.y;
    r.z = (u.z - mean2) * rstd2 * g2v.z + b2v.z;
    r.w = (u.w - mean2) * rstd2 * g2v.w + b2v.w;
    ((float4*)(out + (size_t)row * DIM))[tid] = r;
}

// ---------------- launch ----------------------------------------------------
extern "C" void kernel_launch(void* const* d_in, const int* in_sizes, int n_in,
                              void* d_out, int out_size)
{
    const float* x     = (const float*)d_in[0];
    const int*   amask = (const int*  )d_in[1];
    const float* wq = (const float*)d_in[2];
    const float* bq = (const float*)d_in[3];
    const float* wk = (const float*)d_in[4];
    const float* bk = (const float*)d_in[5];
    const float* wv = (const float*)d_in[6];
    const float* bv = (const float*)d_in[7];
    const float* wo = (const float*)d_in[8];
    const float* bo = (const float*)d_in[9];
    const float* ln1_g = (const float*)d_in[10];
    const float* ln1_b = (const float*)d_in[11];
    const float* w1 = (const float*)d_in[12];
    const float* b1 = (const float*)d_in[13];
    const float* w2 = (const float*)d_in[14];
    const float* b2 = (const float*)d_in[15];
    const float* lnf_g = (const float*)d_in[16];
    const float* lnf_b = (const float*)d_in[17];
    const float* ln2_g = (const float*)d_in[18];
    const float* ln2_b = (const float*)d_in[19];
    float* out = (float*)d_out;

    float *tmp, *x1, *bqkv;
    cudaGetSymbolAddress((void**)&tmp,  g_tmp);
    cudaGetSymbolAddress((void**)&x1,   g_x1);
    cudaGetSymbolAddress((void**)&bqkv, g_bqkv);

    __half *xh,*qkv,*ctxh,*x1h,*hh,*wqkvh,*woh,*w1h,*w2h;
    cudaGetSymbolAddress((void**)&xh,   g_x);
    cudaGetSymbolAddress((void**)&qkv,  g_qkv);
    cudaGetSymbolAddress((void**)&ctxh, g_ctx);
    cudaGetSymbolAddress((void**)&x1h,  g_x1h);
    cudaGetSymbolAddress((void**)&hh,   g_h);
    cudaGetSymbolAddress((void**)&wqkvh,g_wqkv);
    cudaGetSymbolAddress((void**)&woh,  g_wo);
    cudaGetSymbolAddress((void**)&w1h,  g_w1);
    cudaGetSymbolAddress((void**)&w2h,  g_w2);

    cudaFuncSetAttribute(flash_attn_fp16,
                         cudaFuncAttributeMaxDynamicSharedMemorySize, FA_SMEM);
    cudaFuncSetAttribute(hmma_gemm<false,false,true,true>,
                         cudaFuncAttributeMaxDynamicSharedMemorySize, HG_SMEM);
    cudaFuncSetAttribute(hmma_gemm<false,true,false,false>,
                         cudaFuncAttributeMaxDynamicSharedMemorySize, HG_SMEM);
    cudaFuncSetAttribute(hmma_gemm<true,false,true,false>,
                         cudaFuncAttributeMaxDynamicSharedMemorySize, HG_SMEM);

    const dim3 blk(256);
    const dim3 blkG(128);   // GEMM: 4 warps, 64x64 warp tiles, BK=32

    // one fused prep kernel
    prep_all<<<NB_PREP, blk>>>(x, wq, wk, wv, wo, w1, w2, bq, bk, bv,
                               xh, wqkvh, woh, w1h, w2h, bqkv);

    // fused QKV projection (N = 3072), Q columns pre-scaled by 1/8
    hmma_gemm<false,false,true,true><<<dim3(QKVD/128, MTOK/128), blkG, HG_SMEM>>>(
        xh, wqkvh, bqkv, nullptr, qkv, MTOK, QKVD, DIM);

    // attention -> ctx fp16
    flash_attn_fp16<<<dim3(SEQ/128, BATCH*NH), blk, FA_SMEM>>>(
        qkv, amask, ctxh);

    // O projection + residual LN1 (emit x1 fp16)
    hmma_gemm<false,true,false,false><<<dim3(DIM/128, MTOK/128), blkG, HG_SMEM>>>(
        ctxh, woh, bo, tmp, nullptr, MTOK, DIM, DIM);
    ln_residual<true><<<MTOK, blk>>>(x, tmp, ln1_g, ln1_b, x1, x1h, 1e-5f);

    // FFN
    hmma_gemm<true,false,true,false><<<dim3(FFD/128, MTOK/128), blkG, HG_SMEM>>>(
        x1h, w1h, b1, nullptr, hh, MTOK, FFD, DIM);
    hmma_gemm<false,true,false,false><<<dim3(DIM/128, MTOK/128), blkG, HG_SMEM>>>(
        hh, w2h, b2, tmp, nullptr, MTOK, DIM, FFD);

    // fused LNf + LN2
    ln_double<<<MTOK, blk>>>(tmp, x1, lnf_g, lnf_b, ln2_g, ln2_b, out);
}